// round 16
// baseline (speedup 1.0000x reference)
#include <cuda_runtime.h>
#include <math.h>

#define NTHR 512
#define TRIPS 16
#define NBLK 2048
typedef unsigned long long ull;

// smem float offsets
#define WBUF0 0        // 7500: Ws|Wg|Wv parity-0
#define WBUF1 7500     // 7500: parity-1 (pre-loop alias: HIDS [6][64][16])
#define HIDS  7500
#define GEOS  15000    // [16][40]
#define TST   15640    // [16][600]
#define OF_H  0        // float4[50]
#define OF_VC 200      // [50][8]
#define TSF   600
#define SMEM_FLOATS 25240
#define SMEM_BYTES  (SMEM_FLOATS * 4)   // 100960

__device__ float g_s1[6][50];
__device__ float g_w1[6][256];
__device__ float g_walls[32768][6][104];   // edge-0 radial weights (global scratch)

__device__ __forceinline__ float sigm_f(float x) { return 1.0f / (1.0f + __expf(-x)); }
__device__ __forceinline__ float silu_f(float x) { return x / (1.0f + __expf(-x)); }
__device__ __forceinline__ ull fma2(ull a, ull b, ull c) {
    ull d; asm("fma.rn.f32x2 %0, %1, %2, %3;" : "=l"(d) : "l"(a), "l"(b), "l"(c)); return d;
}
__device__ __forceinline__ ull pack2(float lo, float hi) {
    ull d; asm("mov.b64 %0, {%1, %2};" : "=l"(d) : "f"(lo), "f"(hi)); return d;
}
__device__ __forceinline__ void unpack2(ull v, float& lo, float& hi) {
    asm("mov.b64 {%0, %1}, %2;" : "=f"(lo), "=f"(hi) : "l"(v));
}

// Fused: apply edge messages for the NEXT layer to register state, store once.
__device__ __forceinline__ void msg_store(
    float* st, int kx, const float* g,
    float s4, float s3, float s5,
    float v4x, float v4y, float v3x, float v3y, float v3z,
    float v5x, float v5y, float v5z,
    float w0a, float w0b, float s1v,
    float w1a, float w1b, float w1c, float w1d, float w1e)
{
    float u0x = g[0], u0y = g[1], u1x = g[2], u1y = g[3];
    float Y0 = g[19], Y1 = g[20], Y2v = g[21], Y3 = g[22], Y4 = g[23], Y5 = g[24];
    float h4 = s4 + w0a * s1v;
    float base = w1a * s4, a_ = w1b * s4, w01 = w0b * s1v;
    float dot = v4x * u1x + v4y * u1y;
    float wd = w1c * dot;
    float crz = v4x * u1y - v4y * u1x;            // v4z == 0 invariant
    float yx  = v4x * Y0 + v4y * Y3;
    float yy2 = v4x * Y1 + v4y * Y4;
    float yz  = v4x * Y2v + v4y * Y5;
    float axu = a_ * u1x, ayu = a_ * u1y, bz = w1d * crz;
    float cx2 = w1e * yx, cy2 = w1e * yy2, cz2 = w1e * yz;
    *(float4*)(st + OF_H + kx * 4) = make_float4(h4, s3 + base + wd, s5 + base - wd, 0.f);
    *(float4*)(st + OF_VC + kx * 8) =
        make_float4(v4x + w01 * u0x, v4y + w01 * u0y, v3x + axu + cx2, v3y + ayu + cy2);
    *(float4*)(st + OF_VC + kx * 8 + 4) =
        make_float4(v3z + bz + cz2, v5x - axu + cx2, v5y - ayu + cy2, v5z - bz + cz2);
}

__global__ void setup_kernel(const float* __restrict__ We, const float* __restrict__ Wr1g,
                             const float* __restrict__ br1g, const float* __restrict__ Wr2g,
                             const float* __restrict__ Wsg) {
    __shared__ float hid[64];
    __shared__ float s[50];
    __shared__ float sn[50];
    int k = threadIdx.x;
    const float fc = 0.5f * (cosf(3.14159265358979f * (0.05f / 0.06f)) + 1.0f);
    if (k < 50) s[k] = We[k] + We[50 + k];
    for (int l = 0; l < 6; l++) {
        __syncthreads();
        if (k < 64) {
            float acc = br1g[l * 64 + k];
            #pragma unroll
            for (int ib = 0; ib < 10; ib++) {
                float z = 7.5f - (float)ib;
                acc += __expf(-z * z) * fc * Wr1g[l * 768 + ib * 64 + k];
            }
            acc += Wr1g[l * 768 + 11 * 64 + k];
            hid[k] = silu_f(acc);
        }
        if (k < 50) {
            g_s1[l][k] = s[k];
            float acc = 0.f;
            for (int c = 0; c < 50; c++) acc += s[c] * Wsg[l * 2500 + c * 50 + k];
            sn[k] = silu_f(acc);
        }
        __syncthreads();
        if (k < 50) s[k] = sn[k];
        if (k < 250) {
            float acc = 0.f;
            for (int j = 0; j < 64; j++) acc += hid[j] * Wr2g[l * 16000 + j * 250 + k];
            g_w1[l][k] = acc * fc;
        }
    }
}

__global__ void __launch_bounds__(NTHR, 2)
e3nn_kernel(const float* __restrict__ y, const float* __restrict__ Wemb,
            const float* __restrict__ Wr1g, const float* __restrict__ br1g,
            const float* __restrict__ Wr2g, const float* __restrict__ Wsg,
            const float* __restrict__ Wvg, const float* __restrict__ Wgg,
            const float* __restrict__ Woutg, float* __restrict__ outp)
{
    extern __shared__ float sm[];
    const int tid  = threadIdx.x;
    const int w    = tid >> 5;          // warp = trip
    const int lane = tid & 31;
    float* g  = sm + GEOS + w * 40;
    float* st = sm + TST + w * TSF;
    const int t = blockIdx.x * TRIPS + w;
    const int b = t >> 9;
    const int i = t & 511;
    const int k2 = 2 * lane;

    // ---- geometry (warp-local) ----
    if (lane < 2) {
        const float* yy = y + (size_t)(b * 514 + i + lane) * 6;
        float a = yy[2];
        float* bs = g + 28 + lane * 4;
        bs[0] = yy[0]; bs[1] = yy[1];
        bs[2] = -0.05f * sinf(a); bs[3] = 0.05f * cosf(a);
    }
    __syncwarp();
    if (lane == 0) {
        float vx = g[28] - g[32], vy = g[29] - g[33];   // edge 1->4
        float r = sqrtf(vx * vx + vy * vy);
        float inv = 1.0f / (r + 1e-12f);
        g[0] = vx * inv; g[1] = vy * inv;
        float ox = g[34], oy = g[35];
        g[2] = -ox * 20.f; g[3] = -oy * 20.f;           // u1 = -off/0.05
        float tt = fminf(r * (1.0f / 0.06f), 1.0f);
        float fc = 0.5f * (cosf(3.14159265358979f * tt) + 1.0f);
        g[16] = fc;
        #pragma unroll
        for (int ib = 0; ib < 10; ib++) {
            float z = r * 150.f - (float)ib;
            g[4 + ib] = __expf(-z * z) * fc;
        }
        g[14] = 1.f; g[15] = 0.f;
        g[17] = ox; g[18] = oy;
        float u3[3] = {g[2], g[3], 0.f};
        #pragma unroll
        for (int rr = 0; rr < 3; rr++)
            #pragma unroll
            for (int cc = 0; cc < 3; cc++)
                g[19 + rr * 3 + cc] = u3[rr] * u3[cc] - (rr == cc ? (1.f / 3.f) : 0.f);
    }
    __syncwarp();

    // ---- pre-loop A: edge-0 hidden, all 6 layers, trip-minor in WBUF1 ----
    {
        const float fcut0 = g[16];
        #pragma unroll
        for (int l = 0; l < 6; l++) {
            #pragma unroll
            for (int h2 = 0; h2 < 2; h2++) {
                int kk = lane + 32 * h2;
                float acc = __ldg(br1g + l * 64 + kk);
                const float* wr1 = Wr1g + l * 768 + kk;
                #pragma unroll
                for (int ii = 0; ii < 12; ii++) acc += g[4 + ii] * __ldg(wr1 + ii * 64);
                sm[HIDS + (l * 64 + kk) * 16 + w] = silu_f(acc) * fcut0;
            }
        }
    }
    __syncthreads();

    // ---- pre-loop B (warps 0-11 -> g_walls) + layer-0 weight staging (warps 12-15) ----
    if (w < 12) {
        const int l = w >> 1;
        const int pk = ((w & 1) << 5) + lane;
        if (pk < 50) {
            const float* wb2 = Wr2g + (size_t)l * 16000 + 2 * pk;
            #pragma unroll
            for (int tg = 0; tg < 2; tg++) {
                const float* hb = sm + HIDS + l * 1024 + 8 * tg;
                ull a0 = 0, a1 = 0, a2 = 0, a3 = 0, a4 = 0, a5 = 0, a6 = 0, a7 = 0;
                #pragma unroll 4
                for (int j = 0; j < 64; j++) {
                    ull wv = __ldg((const ull*)(wb2 + (size_t)j * 250));
                    float4 ha = *(const float4*)(hb + j * 16);
                    float4 hc = *(const float4*)(hb + j * 16 + 4);
                    a0 = fma2(pack2(ha.x, ha.x), wv, a0);
                    a1 = fma2(pack2(ha.y, ha.y), wv, a1);
                    a2 = fma2(pack2(ha.z, ha.z), wv, a2);
                    a3 = fma2(pack2(ha.w, ha.w), wv, a3);
                    a4 = fma2(pack2(hc.x, hc.x), wv, a4);
                    a5 = fma2(pack2(hc.y, hc.y), wv, a5);
                    a6 = fma2(pack2(hc.z, hc.z), wv, a6);
                    a7 = fma2(pack2(hc.w, hc.w), wv, a7);
                }
                const int tbase = blockIdx.x * TRIPS + tg * 8;
                *(ull*)&g_walls[tbase + 0][l][2 * pk] = a0;
                *(ull*)&g_walls[tbase + 1][l][2 * pk] = a1;
                *(ull*)&g_walls[tbase + 2][l][2 * pk] = a2;
                *(ull*)&g_walls[tbase + 3][l][2 * pk] = a3;
                *(ull*)&g_walls[tbase + 4][l][2 * pk] = a4;
                *(ull*)&g_walls[tbase + 5][l][2 * pk] = a5;
                *(ull*)&g_walls[tbase + 6][l][2 * pk] = a6;
                *(ull*)&g_walls[tbase + 7][l][2 * pk] = a7;
            }
        }
    } else {
        float4* dst = (float4*)(sm + WBUF0);
        const float4* ws4 = (const float4*)Wsg;
        const float4* wg4 = (const float4*)Wgg;
        const float4* wv4 = (const float4*)Wvg;
        for (int idx = tid - 384; idx < 625; idx += 128) {
            dst[idx] = ws4[idx];
            dst[idx + 625] = wg4[idx];
            dst[idx + 1250] = wv4[idx];
        }
    }
    __syncthreads();

    // ================= layer 0 (reduced) + fused message(1) =================
    {
        const float* wb = sm + WBUF0;
        if (lane < 25) {
            const ull* wlp = (const ull*)&g_walls[t][0][0];
            float w0a0, w0a1, w0b0, w0b1;
            unpack2(__ldg(wlp + lane), w0a0, w0a1);
            unpack2(__ldg(wlp + 25 + lane), w0b0, w0b1);
            float s1a, s1b; unpack2(__ldg((const ull*)&g_s1[0][k2]), s1a, s1b);
            float w1aa, w1ab; unpack2(__ldg((const ull*)&g_w1[0][k2]), w1aa, w1ab);
            float w1ba, w1bb; unpack2(__ldg((const ull*)(g_w1[0] + 50 + k2)), w1ba, w1bb);
            #pragma unroll
            for (int kk = 0; kk < 2; kk++) {
                int kx = k2 + kk;
                float e0 = __ldg(Wemb + kx), e1 = __ldg(Wemb + 50 + kx), e2 = __ldg(Wemb + 100 + kx);
                float s4i = e0 + e1, s3i = e0 + e2;
                float s1v = kk ? s1b : s1a;
                float h4 = s4i + (kk ? w0a1 : w0a0) * s1v;
                float h3 = s3i + (kk ? w1ab : w1aa) * s4i;
                float p = (kk ? w0b1 : w0b0) * s1v;
                float q = (kk ? w1bb : w1ba) * s4i;
                *(float4*)(st + OF_H + kx * 4) = make_float4(h4, h3, 0.f, 0.f);
                *(float2*)(st + OF_VC + kx * 8) = make_float2(p, q);
            }
        }
        __syncwarp();
        if (lane < 25) {
            ull as4 = 0, as3 = 0, ag4 = 0, ag3 = 0, ap = 0, aq = 0;
            #pragma unroll 2
            for (int c = 0; c < 50; c++) {
                ull ws = *(const ull*)(wb + c * 50 + k2);
                ull wg = *(const ull*)(wb + 2500 + c * 50 + k2);
                ull wv = *(const ull*)(wb + 5000 + c * 50 + k2);
                float4 h = *(const float4*)(st + OF_H + c * 4);
                float2 pq = *(const float2*)(st + OF_VC + c * 8);
                ull h4d = pack2(h.x, h.x), h3d = pack2(h.y, h.y);
                as4 = fma2(ws, h4d, as4); as3 = fma2(ws, h3d, as3);
                ag4 = fma2(wg, h4d, ag4); ag3 = fma2(wg, h3d, ag3);
                ap = fma2(wv, pack2(pq.x, pq.x), ap);
                aq = fma2(wv, pack2(pq.y, pq.y), aq);
            }
            float s4a, s4b, s3a, s3b, g4a, g4b, g3a, g3b, pa, pb, qa, qb;
            unpack2(as4, s4a, s4b); unpack2(as3, s3a, s3b);
            unpack2(ag4, g4a, g4b); unpack2(ag3, g3a, g3b);
            unpack2(ap, pa, pb); unpack2(aq, qa, qb);
            float u0x = g[0], u0y = g[1], u1x = g[2], u1y = g[3];
            // fused message(1) weights
            const ull* wlp1 = (const ull*)&g_walls[t][1][0];
            float w0a0, w0a1, w0b0, w0b1;
            unpack2(__ldg(wlp1 + lane), w0a0, w0a1);
            unpack2(__ldg(wlp1 + 25 + lane), w0b0, w0b1);
            float s1a, s1b; unpack2(__ldg((const ull*)&g_s1[1][k2]), s1a, s1b);
            const float* w1p = g_w1[1];
            float w1aa, w1ab, w1ba, w1bb, w1ca, w1cb, w1da, w1db, w1ea, w1eb;
            unpack2(__ldg((const ull*)(w1p + k2)), w1aa, w1ab);
            unpack2(__ldg((const ull*)(w1p + 50 + k2)), w1ba, w1bb);
            unpack2(__ldg((const ull*)(w1p + 100 + k2)), w1ca, w1cb);
            unpack2(__ldg((const ull*)(w1p + 150 + k2)), w1da, w1db);
            unpack2(__ldg((const ull*)(w1p + 200 + k2)), w1ea, w1eb);
            #pragma unroll
            for (int kk = 0; kk < 2; kk++) {
                int kx = k2 + kk;
                float s4 = silu_f(kk ? s4b : s4a), s3 = silu_f(kk ? s3b : s3a);
                float g4 = sigm_f(kk ? g4b : g4a), g3 = sigm_f(kk ? g3b : g3a);
                float P = (kk ? pb : pa) * g4, Q = (kk ? qb : qa) * g3;
                float v4x = P * u0x, v4y = P * u0y;
                float v3x = Q * u1x, v3y = Q * u1y;
                msg_store(st, kx, g, s4, s3, s3,
                          v4x, v4y, v3x, v3y, 0.f, -v3x, -v3y, 0.f,
                          kk ? w0a1 : w0a0, kk ? w0b1 : w0b0, kk ? s1b : s1a,
                          kk ? w1ab : w1aa, kk ? w1bb : w1ba, kk ? w1cb : w1ca,
                          kk ? w1db : w1da, kk ? w1eb : w1ea);
            }
        }
        // stage layer-1 weights into WBUF1
        {
            float4* dst = (float4*)(sm + WBUF1);
            const float4* ws4 = (const float4*)(Wsg + 2500);
            const float4* wg4 = (const float4*)(Wgg + 2500);
            const float4* wv4 = (const float4*)(Wvg + 2500);
            for (int idx = tid; idx < 625; idx += NTHR) {
                dst[idx] = ws4[idx];
                dst[idx + 625] = wg4[idx];
                dst[idx + 1250] = wv4[idx];
            }
        }
        __syncthreads();
    }

    // ================= layers 1..5: GEMM -> epilogue(+fused message) =================
    for (int l = 1; l < 6; l++) {
        const float* wb = sm + (l & 1) * 7500;
        if (lane < 25) {
            // pass 1: s + gate GEMM
            ull as4 = 0, as3 = 0, as5 = 0, ag4 = 0, ag3 = 0, ag5 = 0;
            {
                const float* hb = st + OF_H;
                #pragma unroll 2
                for (int c = 0; c < 50; c++) {
                    ull ws = *(const ull*)(wb + c * 50 + k2);
                    ull wg = *(const ull*)(wb + 2500 + c * 50 + k2);
                    float4 h = *(const float4*)(hb + c * 4);
                    ull h4d = pack2(h.x, h.x), h3d = pack2(h.y, h.y), h5d = pack2(h.z, h.z);
                    as4 = fma2(ws, h4d, as4); as3 = fma2(ws, h3d, as3); as5 = fma2(ws, h5d, as5);
                    ag4 = fma2(wg, h4d, ag4); ag3 = fma2(wg, h3d, ag3); ag5 = fma2(wg, h5d, ag5);
                }
            }
            float s4a, s4b, s3a, s3b, s5a, s5b;
            unpack2(as4, s4a, s4b); unpack2(as3, s3a, s3b); unpack2(as5, s5a, s5b);
            s4a = silu_f(s4a); s4b = silu_f(s4b);
            s3a = silu_f(s3a); s3b = silu_f(s3b);
            s5a = silu_f(s5a); s5b = silu_f(s5b);
            float g4a, g4b, g3a, g3b, g5a, g5b;
            unpack2(ag4, g4a, g4b); unpack2(ag3, g3a, g3b); unpack2(ag5, g5a, g5b);
            g4a = sigm_f(g4a); g4b = sigm_f(g4b);
            g3a = sigm_f(g3a); g3b = sigm_f(g3b);
            g5a = sigm_f(g5a); g5b = sigm_f(g5b);
            // pass 2: v GEMM
            ull a0 = 0, a1 = 0, a2 = 0, a3 = 0, a4 = 0, a5 = 0, a6 = 0, a7 = 0;
            {
                const float* vcb = st + OF_VC;
                const float* wvb = wb + 5000;
                #pragma unroll 2
                for (int c = 0; c < 50; c++) {
                    ull wv = *(const ull*)(wvb + c * 50 + k2);
                    float4 va = *(const float4*)(vcb + c * 8);
                    float4 vb = *(const float4*)(vcb + c * 8 + 4);
                    a0 = fma2(wv, pack2(va.x, va.x), a0);
                    a1 = fma2(wv, pack2(va.y, va.y), a1);
                    a2 = fma2(wv, pack2(va.z, va.z), a2);
                    a3 = fma2(wv, pack2(va.w, va.w), a3);
                    a4 = fma2(wv, pack2(vb.x, vb.x), a4);
                    a5 = fma2(wv, pack2(vb.y, vb.y), a5);
                    a6 = fma2(wv, pack2(vb.z, vb.z), a6);
                    a7 = fma2(wv, pack2(vb.w, vb.w), a7);
                }
            }
            // epilogue (+ fused message l+1)
            if (l < 5) {
                const ull* wlp = (const ull*)&g_walls[t][l + 1][0];
                float w0a0, w0a1, w0b0, w0b1;
                unpack2(__ldg(wlp + lane), w0a0, w0a1);
                unpack2(__ldg(wlp + 25 + lane), w0b0, w0b1);
                float s1a, s1b; unpack2(__ldg((const ull*)&g_s1[l + 1][k2]), s1a, s1b);
                const float* w1p = g_w1[l + 1];
                float w1aa, w1ab, w1ba, w1bb, w1ca, w1cb, w1da, w1db, w1ea, w1eb;
                unpack2(__ldg((const ull*)(w1p + k2)), w1aa, w1ab);
                unpack2(__ldg((const ull*)(w1p + 50 + k2)), w1ba, w1bb);
                unpack2(__ldg((const ull*)(w1p + 100 + k2)), w1ca, w1cb);
                unpack2(__ldg((const ull*)(w1p + 150 + k2)), w1da, w1db);
                unpack2(__ldg((const ull*)(w1p + 200 + k2)), w1ea, w1eb);
                #pragma unroll
                for (int kk = 0; kk < 2; kk++) {
                    int kx = k2 + kk;
                    float s4 = kk ? s4b : s4a, s3 = kk ? s3b : s3a, s5 = kk ? s5b : s5a;
                    float g4 = kk ? g4b : g4a, g3 = kk ? g3b : g3a, g5 = kk ? g5b : g5a;
                    float V4x, V4y, V3x, V3y, V3z, V5x, V5y, V5z, xx;
                    if (kk == 0) {
                        unpack2(a0, V4x, xx); unpack2(a1, V4y, xx);
                        unpack2(a2, V3x, xx); unpack2(a3, V3y, xx);
                        unpack2(a4, V3z, xx); unpack2(a5, V5x, xx);
                        unpack2(a6, V5y, xx); unpack2(a7, V5z, xx);
                    } else {
                        unpack2(a0, xx, V4x); unpack2(a1, xx, V4y);
                        unpack2(a2, xx, V3x); unpack2(a3, xx, V3y);
                        unpack2(a4, xx, V3z); unpack2(a5, xx, V5x);
                        unpack2(a6, xx, V5y); unpack2(a7, xx, V5z);
                    }
                    msg_store(st, kx, g, s4, s3, s5,
                              V4x * g4, V4y * g4, V3x * g3, V3y * g3, V3z * g3,
                              V5x * g5, V5y * g5, V5z * g5,
                              kk ? w0a1 : w0a0, kk ? w0b1 : w0b0, kk ? s1b : s1a,
                              kk ? w1ab : w1aa, kk ? w1bb : w1ba, kk ? w1cb : w1ca,
                              kk ? w1db : w1da, kk ? w1eb : w1ea);
                }
            } else {
                #pragma unroll
                for (int kk = 0; kk < 2; kk++) {
                    int kx = k2 + kk;
                    float g4 = kk ? g4b : g4a, g3 = kk ? g3b : g3a, g5 = kk ? g5b : g5a;
                    float V4x, V4y, V3x, V3y, V3z, V5x, V5y, V5z, xx;
                    if (kk == 0) {
                        unpack2(a0, V4x, xx); unpack2(a1, V4y, xx);
                        unpack2(a2, V3x, xx); unpack2(a3, V3y, xx);
                        unpack2(a4, V3z, xx); unpack2(a5, V5x, xx);
                        unpack2(a6, V5y, xx); unpack2(a7, V5z, xx);
                    } else {
                        unpack2(a0, xx, V4x); unpack2(a1, xx, V4y);
                        unpack2(a2, xx, V3x); unpack2(a3, xx, V3y);
                        unpack2(a4, xx, V3z); unpack2(a5, xx, V5x);
                        unpack2(a6, xx, V5y); unpack2(a7, xx, V5z);
                    }
                    *(float4*)(st + OF_VC + kx * 8) =
                        make_float4(V4x * g4, V4y * g4, V3x * g3, V3y * g3);
                    *(float4*)(st + OF_VC + kx * 8 + 4) =
                        make_float4(V3z * g3, V5x * g5, V5y * g5, V5z * g5);
                }
            }
        }
        if (l < 5) {
            float4* dst = (float4*)(sm + ((l + 1) & 1) * 7500);
            const float4* ws4 = (const float4*)(Wsg + (size_t)(l + 1) * 2500);
            const float4* wg4 = (const float4*)(Wgg + (size_t)(l + 1) * 2500);
            const float4* wv4 = (const float4*)(Wvg + (size_t)(l + 1) * 2500);
            for (int idx = tid; idx < 625; idx += NTHR) {
                dst[idx] = ws4[idx];
                dst[idx + 625] = wg4[idx];
                dst[idx + 1250] = wv4[idx];
            }
            __syncthreads();
        }
    }
    __syncwarp();

    // ---- output epilogue (warp-local) ----
    if (lane < 6) {
        int off = lane < 4 ? lane : lane + 1;   // n4{0,1} n3{2,3} n5{5,6}
        float acc = 0.f;
        #pragma unroll 5
        for (int c = 0; c < 50; c++) acc += st[OF_VC + c * 8 + off] * __ldg(Woutg + c);
        g[28 + lane] = acc;
    }
    __syncwarp();
    if (lane == 0) {
        float o4x = g[28], o4y = g[29], o3x = g[30], o3y = g[31], o5x = g[32], o5y = g[33];
        float ox = g[17], oy = g[18];
        float* dst = outp + (size_t)(b * 514 + i + 1) * 3;
        dst[0] = o3x + o4x + o5x;
        dst[1] = o3y + o4y + o5y;
        dst[2] = ox * (o3y - o5y) - oy * (o3x - o5x);
    }
}

extern "C" void kernel_launch(void* const* d_in, const int* in_sizes, int n_in,
                              void* d_out, int out_size) {
    const float* y    = (const float*)d_in[0];
    const float* Wemb = (const float*)d_in[1];
    const float* Wr1  = (const float*)d_in[2];
    const float* br1  = (const float*)d_in[3];
    const float* Wr2  = (const float*)d_in[4];
    const float* Ws   = (const float*)d_in[5];
    const float* Wv   = (const float*)d_in[6];
    const float* Wg   = (const float*)d_in[7];
    const float* Wo   = (const float*)d_in[8];
    float* outp = (float*)d_out;

    cudaMemsetAsync(outp, 0, (size_t)out_size * sizeof(float));
    setup_kernel<<<1, 256>>>(Wemb, Wr1, br1, Wr2, Ws);
    cudaFuncSetAttribute(e3nn_kernel, cudaFuncAttributeMaxDynamicSharedMemorySize, SMEM_BYTES);
    e3nn_kernel<<<NBLK, NTHR, SMEM_BYTES>>>(y, Wemb, Wr1, br1, Wr2, Ws, Wv, Wg, Wo, outp);
}

// round 17
// speedup vs baseline: 1.1354x; 1.1354x over previous
#include <cuda_runtime.h>
#include <math.h>

#define NTHR 512
#define TRIPS 16
#define NBLK 2048
typedef unsigned long long ull;

// smem float offsets
#define WBUF0 0        // 7500: Ws|Wg|Wv parity-0
#define WBUF1 7500     // 7500: parity-1 (pre-loop alias: HIDS [6][64][16])
#define HIDS  7500
#define GEOS  15000    // [16][40]
#define TST   15640    // [16][600]
#define OF_H   0       // [2][25][4] channel-deinterleaved: chof(kx)
#define OF_VCA 200     // [2][25][4]: comps {v4x,v4y,v3x,v3y}
#define OF_VCB 400     // [2][25][4]: comps {v3z,v5x,v5y,v5z}
#define TSF   600
#define SMEM_FLOATS 25240
#define SMEM_BYTES  (SMEM_FLOATS * 4)   // 100960

__device__ float g_s1[6][50];
__device__ float g_w1[6][256];
__device__ float g_walls[32768][6][104];   // edge-0 radial weights (global scratch)

__device__ __forceinline__ int chof(int kx) { return ((kx & 1) * 100) + ((kx >> 1) << 2); }

__device__ __forceinline__ float sigm_f(float x) { return 1.0f / (1.0f + __expf(-x)); }
__device__ __forceinline__ float silu_f(float x) { return x / (1.0f + __expf(-x)); }
__device__ __forceinline__ ull fma2(ull a, ull b, ull c) {
    ull d; asm("fma.rn.f32x2 %0, %1, %2, %3;" : "=l"(d) : "l"(a), "l"(b), "l"(c)); return d;
}
__device__ __forceinline__ ull pack2(float lo, float hi) {
    ull d; asm("mov.b64 %0, {%1, %2};" : "=l"(d) : "f"(lo), "f"(hi)); return d;
}
__device__ __forceinline__ void unpack2(ull v, float& lo, float& hi) {
    asm("mov.b64 {%0, %1}, %2;" : "=f"(lo), "=f"(hi) : "l"(v));
}

__global__ void setup_kernel(const float* __restrict__ We, const float* __restrict__ Wr1g,
                             const float* __restrict__ br1g, const float* __restrict__ Wr2g,
                             const float* __restrict__ Wsg) {
    __shared__ float hid[64];
    __shared__ float s[50];
    __shared__ float sn[50];
    int k = threadIdx.x;
    const float fc = 0.5f * (cosf(3.14159265358979f * (0.05f / 0.06f)) + 1.0f);
    if (k < 50) s[k] = We[k] + We[50 + k];
    for (int l = 0; l < 6; l++) {
        __syncthreads();
        if (k < 64) {
            float acc = br1g[l * 64 + k];
            #pragma unroll
            for (int ib = 0; ib < 10; ib++) {
                float z = 7.5f - (float)ib;
                acc += __expf(-z * z) * fc * Wr1g[l * 768 + ib * 64 + k];
            }
            acc += Wr1g[l * 768 + 11 * 64 + k];
            hid[k] = silu_f(acc);
        }
        if (k < 50) {
            g_s1[l][k] = s[k];
            float acc = 0.f;
            for (int c = 0; c < 50; c++) acc += s[c] * Wsg[l * 2500 + c * 50 + k];
            sn[k] = silu_f(acc);
        }
        __syncthreads();
        if (k < 50) s[k] = sn[k];
        if (k < 250) {
            float acc = 0.f;
            for (int j = 0; j < 64; j++) acc += hid[j] * Wr2g[l * 16000 + j * 250 + k];
            g_w1[l][k] = acc * fc;
        }
    }
}

__global__ void __launch_bounds__(NTHR, 2)
e3nn_kernel(const float* __restrict__ y, const float* __restrict__ Wemb,
            const float* __restrict__ Wr1g, const float* __restrict__ br1g,
            const float* __restrict__ Wr2g, const float* __restrict__ Wsg,
            const float* __restrict__ Wvg, const float* __restrict__ Wgg,
            const float* __restrict__ Woutg, float* __restrict__ outp)
{
    extern __shared__ float sm[];
    const int tid  = threadIdx.x;
    const int w    = tid >> 5;          // warp = trip
    const int lane = tid & 31;
    float* g  = sm + GEOS + w * 40;
    float* st = sm + TST + w * TSF;
    const int t = blockIdx.x * TRIPS + w;
    const int b = t >> 9;
    const int i = t & 511;
    const int k2 = 2 * lane;

    // ---- geometry (warp-local) ----
    if (lane < 2) {
        const float* yy = y + (size_t)(b * 514 + i + lane) * 6;
        float a = yy[2];
        float* bs = g + 28 + lane * 4;
        bs[0] = yy[0]; bs[1] = yy[1];
        bs[2] = -0.05f * sinf(a); bs[3] = 0.05f * cosf(a);
    }
    __syncwarp();
    if (lane == 0) {
        float vx = g[28] - g[32], vy = g[29] - g[33];   // edge 1->4
        float r = sqrtf(vx * vx + vy * vy);
        float inv = 1.0f / (r + 1e-12f);
        g[0] = vx * inv; g[1] = vy * inv;
        float ox = g[34], oy = g[35];
        g[2] = -ox * 20.f; g[3] = -oy * 20.f;           // u1 = -off/0.05
        float tt = fminf(r * (1.0f / 0.06f), 1.0f);
        float fc = 0.5f * (cosf(3.14159265358979f * tt) + 1.0f);
        g[16] = fc;
        #pragma unroll
        for (int ib = 0; ib < 10; ib++) {
            float z = r * 150.f - (float)ib;
            g[4 + ib] = __expf(-z * z) * fc;
        }
        g[14] = 1.f; g[15] = 0.f;
        g[17] = ox; g[18] = oy;
        float u3[3] = {g[2], g[3], 0.f};
        #pragma unroll
        for (int rr = 0; rr < 3; rr++)
            #pragma unroll
            for (int cc = 0; cc < 3; cc++)
                g[19 + rr * 3 + cc] = u3[rr] * u3[cc] - (rr == cc ? (1.f / 3.f) : 0.f);
    }
    __syncwarp();

    // ---- pre-loop A: edge-0 hidden, all 6 layers, trip-minor in WBUF1 ----
    {
        const float fcut0 = g[16];
        #pragma unroll
        for (int l = 0; l < 6; l++) {
            #pragma unroll
            for (int h2 = 0; h2 < 2; h2++) {
                int kk = lane + 32 * h2;
                float acc = __ldg(br1g + l * 64 + kk);
                const float* wr1 = Wr1g + l * 768 + kk;
                #pragma unroll
                for (int ii = 0; ii < 12; ii++) acc += g[4 + ii] * __ldg(wr1 + ii * 64);
                sm[HIDS + (l * 64 + kk) * 16 + w] = silu_f(acc) * fcut0;
            }
        }
    }
    __syncthreads();

    // ---- pre-loop B (warps 0-11 -> g_walls) + layer-0 weight staging (warps 12-15) ----
    if (w < 12) {
        const int l = w >> 1;
        const int pk = ((w & 1) << 5) + lane;
        if (pk < 50) {
            const float* wb2 = Wr2g + (size_t)l * 16000 + 2 * pk;
            #pragma unroll
            for (int tg = 0; tg < 2; tg++) {
                const float* hb = sm + HIDS + l * 1024 + 8 * tg;
                ull a0 = 0, a1 = 0, a2 = 0, a3 = 0, a4 = 0, a5 = 0, a6 = 0, a7 = 0;
                #pragma unroll 4
                for (int j = 0; j < 64; j++) {
                    ull wv = __ldg((const ull*)(wb2 + (size_t)j * 250));
                    float4 ha = *(const float4*)(hb + j * 16);
                    float4 hc = *(const float4*)(hb + j * 16 + 4);
                    a0 = fma2(pack2(ha.x, ha.x), wv, a0);
                    a1 = fma2(pack2(ha.y, ha.y), wv, a1);
                    a2 = fma2(pack2(ha.z, ha.z), wv, a2);
                    a3 = fma2(pack2(ha.w, ha.w), wv, a3);
                    a4 = fma2(pack2(hc.x, hc.x), wv, a4);
                    a5 = fma2(pack2(hc.y, hc.y), wv, a5);
                    a6 = fma2(pack2(hc.z, hc.z), wv, a6);
                    a7 = fma2(pack2(hc.w, hc.w), wv, a7);
                }
                const int tbase = blockIdx.x * TRIPS + tg * 8;
                *(ull*)&g_walls[tbase + 0][l][2 * pk] = a0;
                *(ull*)&g_walls[tbase + 1][l][2 * pk] = a1;
                *(ull*)&g_walls[tbase + 2][l][2 * pk] = a2;
                *(ull*)&g_walls[tbase + 3][l][2 * pk] = a3;
                *(ull*)&g_walls[tbase + 4][l][2 * pk] = a4;
                *(ull*)&g_walls[tbase + 5][l][2 * pk] = a5;
                *(ull*)&g_walls[tbase + 6][l][2 * pk] = a6;
                *(ull*)&g_walls[tbase + 7][l][2 * pk] = a7;
            }
        }
    } else {
        float4* dst = (float4*)(sm + WBUF0);
        const float4* ws4 = (const float4*)Wsg;
        const float4* wg4 = (const float4*)Wgg;
        const float4* wv4 = (const float4*)Wvg;
        for (int idx = tid - 384; idx < 625; idx += 128) {
            dst[idx] = ws4[idx];
            dst[idx + 625] = wg4[idx];
            dst[idx + 1250] = wv4[idx];
        }
    }
    __syncthreads();

    // ================= layer 0 (reduced: h-rows + 2 GEMVs) =================
    {
        const float* wb = sm + WBUF0;
        if (lane < 25) {
            const ull* wlp = (const ull*)&g_walls[t][0][0];
            float w0a0, w0a1, w0b0, w0b1;
            unpack2(__ldg(wlp + lane), w0a0, w0a1);
            unpack2(__ldg(wlp + 25 + lane), w0b0, w0b1);
            float s1a, s1b; unpack2(__ldg((const ull*)&g_s1[0][k2]), s1a, s1b);
            float w1aa, w1ab; unpack2(__ldg((const ull*)&g_w1[0][k2]), w1aa, w1ab);
            float w1ba, w1bb; unpack2(__ldg((const ull*)(g_w1[0] + 50 + k2)), w1ba, w1bb);
            #pragma unroll
            for (int kk = 0; kk < 2; kk++) {
                int kx = k2 + kk;
                int co = chof(kx);
                float e0 = __ldg(Wemb + kx), e1 = __ldg(Wemb + 50 + kx), e2 = __ldg(Wemb + 100 + kx);
                float s4i = e0 + e1, s3i = e0 + e2;
                float s1v = kk ? s1b : s1a;
                float h4 = s4i + (kk ? w0a1 : w0a0) * s1v;
                float h3 = s3i + (kk ? w1ab : w1aa) * s4i;
                float p = (kk ? w0b1 : w0b0) * s1v;
                float q = (kk ? w1bb : w1ba) * s4i;
                *(float4*)(st + OF_H + co) = make_float4(h4, h3, 0.f, 0.f);
                *(float2*)(st + OF_VCA + co) = make_float2(p, q);
            }
        }
        __syncwarp();
        if (lane < 25) {
            ull as4 = 0, as3 = 0, ag4 = 0, ag3 = 0, ap = 0, aq = 0;
            #pragma unroll 2
            for (int c = 0; c < 50; c++) {
                int co = chof(c);
                ull ws = *(const ull*)(wb + c * 50 + k2);
                ull wg = *(const ull*)(wb + 2500 + c * 50 + k2);
                ull wv = *(const ull*)(wb + 5000 + c * 50 + k2);
                float4 h = *(const float4*)(st + OF_H + co);
                float2 pq = *(const float2*)(st + OF_VCA + co);
                ull h4d = pack2(h.x, h.x), h3d = pack2(h.y, h.y);
                as4 = fma2(ws, h4d, as4); as3 = fma2(ws, h3d, as3);
                ag4 = fma2(wg, h4d, ag4); ag3 = fma2(wg, h3d, ag3);
                ap = fma2(wv, pack2(pq.x, pq.x), ap);
                aq = fma2(wv, pack2(pq.y, pq.y), aq);
            }
            float s4a, s4b, s3a, s3b, g4a, g4b, g3a, g3b, pa, pb, qa, qb;
            unpack2(as4, s4a, s4b); unpack2(as3, s3a, s3b);
            unpack2(ag4, g4a, g4b); unpack2(ag3, g3a, g3b);
            unpack2(ap, pa, pb); unpack2(aq, qa, qb);
            float u0x = g[0], u0y = g[1], u1x = g[2], u1y = g[3];
            #pragma unroll
            for (int kk = 0; kk < 2; kk++) {
                int kx = k2 + kk;
                int co = chof(kx);
                float s4 = silu_f(kk ? s4b : s4a), s3 = silu_f(kk ? s3b : s3a);
                float g4 = sigm_f(kk ? g4b : g4a), g3 = sigm_f(kk ? g3b : g3a);
                float P = (kk ? pb : pa) * g4, Q = (kk ? qb : qa) * g3;
                float v4x = P * u0x, v4y = P * u0y;
                float v3x = Q * u1x, v3y = Q * u1y;
                *(float4*)(st + OF_H + co) = make_float4(s4, s3, s3, 0.f);
                *(float4*)(st + OF_VCA + co) = make_float4(v4x, v4y, v3x, v3y);
                *(float4*)(st + OF_VCB + co) = make_float4(0.f, -v3x, -v3y, 0.f);
            }
        }
        // stage layer-1 weights into WBUF1
        {
            float4* dst = (float4*)(sm + WBUF1);
            const float4* ws4 = (const float4*)(Wsg + 2500);
            const float4* wg4 = (const float4*)(Wgg + 2500);
            const float4* wv4 = (const float4*)(Wvg + 2500);
            for (int idx = tid; idx < 625; idx += NTHR) {
                dst[idx] = ws4[idx];
                dst[idx + 625] = wg4[idx];
                dst[idx + 1250] = wv4[idx];
            }
        }
        __syncthreads();
    }

    // ================= layers 1..5: message -> GEMM -> epilogue =================
    for (int l = 1; l < 6; l++) {
        const float* wb = sm + (l & 1) * 7500;
        if (lane < 25) {
            // message phase (warp-local, conflict-free state accesses)
            const ull* wlp = (const ull*)&g_walls[t][l][0];
            float w0a0, w0a1, w0b0, w0b1;
            unpack2(__ldg(wlp + lane), w0a0, w0a1);
            unpack2(__ldg(wlp + 25 + lane), w0b0, w0b1);
            float s1a, s1b; unpack2(__ldg((const ull*)&g_s1[l][k2]), s1a, s1b);
            const float* w1p = g_w1[l];
            float w1aa, w1ab, w1ba, w1bb, w1ca, w1cb, w1da, w1db, w1ea, w1eb;
            unpack2(__ldg((const ull*)(w1p + k2)), w1aa, w1ab);
            unpack2(__ldg((const ull*)(w1p + 50 + k2)), w1ba, w1bb);
            unpack2(__ldg((const ull*)(w1p + 100 + k2)), w1ca, w1cb);
            unpack2(__ldg((const ull*)(w1p + 150 + k2)), w1da, w1db);
            unpack2(__ldg((const ull*)(w1p + 200 + k2)), w1ea, w1eb);
            float u0x = g[0], u0y = g[1], u1x = g[2], u1y = g[3];
            float Y0 = g[19], Y1 = g[20], Y2v = g[21], Y3 = g[22], Y4 = g[23], Y5 = g[24];
            #pragma unroll
            for (int kk = 0; kk < 2; kk++) {
                int kx = k2 + kk;
                int co = chof(kx);
                float w0a = kk ? w0a1 : w0a0, w0b = kk ? w0b1 : w0b0;
                float s1v = kk ? s1b : s1a;
                float w1a = kk ? w1ab : w1aa, w1b = kk ? w1bb : w1ba, w1c = kk ? w1cb : w1ca;
                float w1d = kk ? w1db : w1da, w1e = kk ? w1eb : w1ea;
                float4 s = *(const float4*)(st + OF_H + co);
                float4 va = *(const float4*)(st + OF_VCA + co);
                float4 vb = *(const float4*)(st + OF_VCB + co);
                float h4 = s.x + w0a * s1v;
                float base = w1a * s.x, a_ = w1b * s.x, w01 = w0b * s1v;
                float dot = va.x * u1x + va.y * u1y;
                float wd = w1c * dot;
                float crz = va.x * u1y - va.y * u1x;                  // v4z == 0
                float yx  = va.x * Y0 + va.y * Y3;
                float yy2 = va.x * Y1 + va.y * Y4;
                float yz  = va.x * Y2v + va.y * Y5;
                float axu = a_ * u1x, ayu = a_ * u1y, bz = w1d * crz;
                float cx2 = w1e * yx, cy2 = w1e * yy2, cz2 = w1e * yz;
                *(float4*)(st + OF_H + co) = make_float4(h4, s.y + base + wd, s.z + base - wd, 0.f);
                *(float4*)(st + OF_VCA + co) =
                    make_float4(va.x + w01 * u0x, va.y + w01 * u0y, va.z + axu + cx2, va.w + ayu + cy2);
                *(float4*)(st + OF_VCB + co) =
                    make_float4(vb.x + bz + cz2, vb.y - axu + cx2, vb.z - ayu + cy2, vb.w - bz + cz2);
            }
        }
        __syncwarp();
        if (lane < 25) {
            // pass 1: s + gate GEMM
            ull as4 = 0, as3 = 0, as5 = 0, ag4 = 0, ag3 = 0, ag5 = 0;
            {
                #pragma unroll 2
                for (int c = 0; c < 50; c++) {
                    ull ws = *(const ull*)(wb + c * 50 + k2);
                    ull wg = *(const ull*)(wb + 2500 + c * 50 + k2);
                    float4 h = *(const float4*)(st + OF_H + chof(c));
                    ull h4d = pack2(h.x, h.x), h3d = pack2(h.y, h.y), h5d = pack2(h.z, h.z);
                    as4 = fma2(ws, h4d, as4); as3 = fma2(ws, h3d, as3); as5 = fma2(ws, h5d, as5);
                    ag4 = fma2(wg, h4d, ag4); ag3 = fma2(wg, h3d, ag3); ag5 = fma2(wg, h5d, ag5);
                }
            }
            float s4a, s4b, s3a, s3b, s5a, s5b;
            unpack2(as4, s4a, s4b); unpack2(as3, s3a, s3b); unpack2(as5, s5a, s5b);
            s4a = silu_f(s4a); s4b = silu_f(s4b);
            s3a = silu_f(s3a); s3b = silu_f(s3b);
            s5a = silu_f(s5a); s5b = silu_f(s5b);
            float g4a, g4b, g3a, g3b, g5a, g5b;
            unpack2(ag4, g4a, g4b); unpack2(ag3, g3a, g3b); unpack2(ag5, g5a, g5b);
            g4a = sigm_f(g4a); g4b = sigm_f(g4b);
            g3a = sigm_f(g3a); g3b = sigm_f(g3b);
            g5a = sigm_f(g5a); g5b = sigm_f(g5b);
            // pass 2: v GEMM
            ull a0 = 0, a1 = 0, a2 = 0, a3 = 0, a4 = 0, a5 = 0, a6 = 0, a7 = 0;
            {
                const float* wvb = wb + 5000;
                #pragma unroll 2
                for (int c = 0; c < 50; c++) {
                    int co = chof(c);
                    ull wv = *(const ull*)(wvb + c * 50 + k2);
                    float4 va = *(const float4*)(st + OF_VCA + co);
                    float4 vb = *(const float4*)(st + OF_VCB + co);
                    a0 = fma2(wv, pack2(va.x, va.x), a0);
                    a1 = fma2(wv, pack2(va.y, va.y), a1);
                    a2 = fma2(wv, pack2(va.z, va.z), a2);
                    a3 = fma2(wv, pack2(va.w, va.w), a3);
                    a4 = fma2(wv, pack2(vb.x, vb.x), a4);
                    a5 = fma2(wv, pack2(vb.y, vb.y), a5);
                    a6 = fma2(wv, pack2(vb.z, vb.z), a6);
                    a7 = fma2(wv, pack2(vb.w, vb.w), a7);
                }
            }
            // epilogue
            #pragma unroll
            for (int kk = 0; kk < 2; kk++) {
                int kx = k2 + kk;
                int co = chof(kx);
                float s4 = kk ? s4b : s4a, s3 = kk ? s3b : s3a, s5 = kk ? s5b : s5a;
                float g4 = kk ? g4b : g4a, g3 = kk ? g3b : g3a, g5 = kk ? g5b : g5a;
                float V4x, V4y, V3x, V3y, V3z, V5x, V5y, V5z, xx;
                if (kk == 0) {
                    unpack2(a0, V4x, xx); unpack2(a1, V4y, xx);
                    unpack2(a2, V3x, xx); unpack2(a3, V3y, xx);
                    unpack2(a4, V3z, xx); unpack2(a5, V5x, xx);
                    unpack2(a6, V5y, xx); unpack2(a7, V5z, xx);
                } else {
                    unpack2(a0, xx, V4x); unpack2(a1, xx, V4y);
                    unpack2(a2, xx, V3x); unpack2(a3, xx, V3y);
                    unpack2(a4, xx, V3z); unpack2(a5, xx, V5x);
                    unpack2(a6, xx, V5y); unpack2(a7, xx, V5z);
                }
                *(float4*)(st + OF_H + co) = make_float4(s4, s3, s5, 0.f);
                *(float4*)(st + OF_VCA + co) =
                    make_float4(V4x * g4, V4y * g4, V3x * g3, V3y * g3);
                *(float4*)(st + OF_VCB + co) =
                    make_float4(V3z * g3, V5x * g5, V5y * g5, V5z * g5);
            }
        }
        if (l < 5) {
            float4* dst = (float4*)(sm + ((l + 1) & 1) * 7500);
            const float4* ws4 = (const float4*)(Wsg + (size_t)(l + 1) * 2500);
            const float4* wg4 = (const float4*)(Wgg + (size_t)(l + 1) * 2500);
            const float4* wv4 = (const float4*)(Wvg + (size_t)(l + 1) * 2500);
            for (int idx = tid; idx < 625; idx += NTHR) {
                dst[idx] = ws4[idx];
                dst[idx + 625] = wg4[idx];
                dst[idx + 1250] = wv4[idx];
            }
            __syncthreads();
        }
    }
    __syncwarp();

    // ---- output epilogue (warp-local) ----
    if (lane < 6) {
        int off = lane < 4 ? lane : lane + 1;   // comps: 0,1=v4xy  2,3=v3xy  5,6=v5xy
        float acc = 0.f;
        const int base = off < 4 ? OF_VCA : OF_VCB;
        const int sub = off < 4 ? off : off - 4;
        #pragma unroll 5
        for (int c = 0; c < 50; c++) acc += st[base + chof(c) + sub] * __ldg(Woutg + c);
        g[28 + lane] = acc;
    }
    __syncwarp();
    if (lane == 0) {
        float o4x = g[28], o4y = g[29], o3x = g[30], o3y = g[31], o5x = g[32], o5y = g[33];
        float ox = g[17], oy = g[18];
        float* dst = outp + (size_t)(b * 514 + i + 1) * 3;
        dst[0] = o3x + o4x + o5x;
        dst[1] = o3y + o4y + o5y;
        dst[2] = ox * (o3y - o5y) - oy * (o3x - o5x);
    }
}

extern "C" void kernel_launch(void* const* d_in, const int* in_sizes, int n_in,
                              void* d_out, int out_size) {
    const float* y    = (const float*)d_in[0];
    const float* Wemb = (const float*)d_in[1];
    const float* Wr1  = (const float*)d_in[2];
    const float* br1  = (const float*)d_in[3];
    const float* Wr2  = (const float*)d_in[4];
    const float* Ws   = (const float*)d_in[5];
    const float* Wv   = (const float*)d_in[6];
    const float* Wg   = (const float*)d_in[7];
    const float* Wo   = (const float*)d_in[8];
    float* outp = (float*)d_out;

    cudaMemsetAsync(outp, 0, (size_t)out_size * sizeof(float));
    setup_kernel<<<1, 256>>>(Wemb, Wr1, br1, Wr2, Ws);
    cudaFuncSetAttribute(e3nn_kernel, cudaFuncAttributeMaxDynamicSharedMemorySize, SMEM_BYTES);
    e3nn_kernel<<<NBLK, NTHR, SMEM_BYTES>>>(y, Wemb, Wr1, br1, Wr2, Ws, Wv, Wg, Wo, outp);
}